// round 8
// baseline (speedup 1.0000x reference)
#include <cuda_runtime.h>
#include <cstdint>

#define D 256
#define RT 8      // relations per block in k_rel
#define KT 32     // k-tile width staged in smem
#define PAD 36    // smem row stride (floats): 144B -> 16B aligned, conflict-free
#define NTILE (D / KT)

typedef unsigned long long u64;

// Scratch (no cudaMalloc allowed).
__device__ float g_sub[D];
__device__ float g_r0[D];
__device__ float g_gi[3 * D];
__device__ float g_obj[2048 * D];   // supports up to R=2048 relations (problem has R=1000)

__device__ __forceinline__ float sigmoidf_(float x) { return 1.0f / (1.0f + expf(-x)); }

__device__ __forceinline__ float wredsum(float v) {
#pragma unroll
    for (int o = 16; o; o >>= 1) v += __shfl_xor_sync(0xffffffffu, v, o);
    return v;
}

// packed f32x2 fma: acc = a*b + acc
__device__ __forceinline__ void fma2(u64& acc, u64 a, u64 b) {
    asm("fma.rn.f32x2 %0, %1, %2, %3;" : "=l"(acc) : "l"(a), "l"(b), "l"(acc));
}
__device__ __forceinline__ float unpack_sum(u64 acc) {
    float lo = __uint_as_float((unsigned)(acc & 0xffffffffu));
    float hi = __uint_as_float((unsigned)(acc >> 32));
    return lo + hi;
}

// Coalesced warp dot: row-major W row (256 floats) with vector x.
__device__ __forceinline__ float warp_dot256(const float* __restrict__ Wrow,
                                             const float* __restrict__ x, int lane) {
    const float4* w4 = reinterpret_cast<const float4*>(Wrow);
    const float4* x4 = reinterpret_cast<const float4*>(x);
    float4 a0 = w4[lane],      b0 = x4[lane];
    float4 a1 = w4[lane + 32], b1 = x4[lane + 32];
    float s = a0.x * b0.x + a0.y * b0.y + a0.z * b0.z + a0.w * b0.w
            + a1.x * b1.x + a1.y * b1.y + a1.z * b1.z + a1.w * b1.w;
    return wredsum(s);
}

// ---------------------------------------------------------------------------
// Prolog A/B/C — warp-per-output, coalesced (proven ~8us total incl launches).
// ---------------------------------------------------------------------------
__global__ void kA_sub(const float* __restrict__ mask, const float* __restrict__ sub_W,
                       const float* __restrict__ sub_b) {
    int lane = threadIdx.x & 31;
    int j = blockIdx.x * 8 + (threadIdx.x >> 5);
    float s = warp_dot256(sub_W + (size_t)j * D, mask, lane);
    if (lane == 0) g_sub[j] = tanhf(s + sub_b[j]);
}

__global__ void kB_r0(const float* __restrict__ enc, const float* __restrict__ W_ih,
                      const float* __restrict__ W_hh, const float* __restrict__ b_ih,
                      const float* __restrict__ b_hh) {
    int lane = threadIdx.x & 31;
    int j = blockIdx.x * 8 + (threadIdx.x >> 5);
    float gi[3], gh[3];
#pragma unroll
    for (int g = 0; g < 3; g++) {
        int row = g * D + j;
        gi[g] = warp_dot256(W_ih + (size_t)row * D, enc, lane);
        gh[g] = warp_dot256(W_hh + (size_t)row * D, g_sub, lane);
    }
    if (lane == 0) {
        float rg = sigmoidf_(gi[0] + b_ih[j] + gh[0] + b_hh[j]);
        float zg = sigmoidf_(gi[1] + b_ih[D + j] + gh[1] + b_hh[D + j]);
        float ng = tanhf(gi[2] + b_ih[2 * D + j] + rg * (gh[2] + b_hh[2 * D + j]));
        g_r0[j] = (1.0f - zg) * ng + zg * g_sub[j];
    }
}

__global__ void kC_gi(const float* __restrict__ W_ih, const float* __restrict__ b_ih) {
    int lane = threadIdx.x & 31;
    int j = blockIdx.x * 8 + (threadIdx.x >> 5);   // 0..767
    float s = warp_dot256(W_ih + (size_t)j * D, g_r0, lane);
    if (lane == 0) g_gi[j] = s + b_ih[j];
}

// ---------------------------------------------------------------------------
// k_rel — EXACT R3 engine (best measured: 38.5us). 256 threads, RT=8,
// smem-staged W (coalesced LDG.128, conflict-free PAD=36), packed f32x2 FMA.
// ---------------------------------------------------------------------------
__global__ void __launch_bounds__(256, 1)
k_rel(const float* __restrict__ rel_table, const float* __restrict__ W_hh,
      const float* __restrict__ b_hh, const float* __restrict__ obj_W,
      const float* __restrict__ obj_b, int R) {
    extern __shared__ float sm[];
    float* sW   = sm;                        // 3 * D * PAD floats
    float* s_h  = sm + 3 * D * PAD;          // RT * D
    float* s_rj = s_h + RT * D;              // RT * D

    int t = threadIdx.x;
    int rbase = blockIdx.x * RT;

#pragma unroll
    for (int r = 0; r < RT; r++)
        s_h[r * D + t] = (rbase + r < R) ? rel_table[(size_t)(rbase + r) * D + t] : 0.0f;

    u64 accR[RT], accZ[RT], accN[RT];
#pragma unroll
    for (int r = 0; r < RT; r++) { accR[r] = 0; accZ[r] = 0; accN[r] = 0; }

    for (int tile = 0; tile < NTILE; tile++) {
        __syncthreads();
#pragma unroll
        for (int i = 0; i < (3 * D * KT / 4) / 256; i++) {   // 24 float4 per thread
            int lin = (i * 256 + t) * 4;
            int row = lin / KT;
            int k   = lin % KT;
            float4 v = *reinterpret_cast<const float4*>(
                &W_hh[(size_t)row * D + tile * KT + k]);
            *reinterpret_cast<float4*>(&sW[row * PAD + k]) = v;
        }
        __syncthreads();
#pragma unroll
        for (int kk = 0; kk < KT; kk += 4) {
            int kg = tile * KT + kk;
            ulonglong2 h2[RT];
#pragma unroll
            for (int r = 0; r < RT; r++)
                h2[r] = *reinterpret_cast<const ulonglong2*>(&s_h[r * D + kg]);
            ulonglong2 wr = *reinterpret_cast<const ulonglong2*>(&sW[(0 * D + t) * PAD + kk]);
            ulonglong2 wz = *reinterpret_cast<const ulonglong2*>(&sW[(1 * D + t) * PAD + kk]);
            ulonglong2 wn = *reinterpret_cast<const ulonglong2*>(&sW[(2 * D + t) * PAD + kk]);
#pragma unroll
            for (int r = 0; r < RT; r++) {
                fma2(accR[r], wr.x, h2[r].x); fma2(accR[r], wr.y, h2[r].y);
                fma2(accZ[r], wz.x, h2[r].x); fma2(accZ[r], wz.y, h2[r].y);
                fma2(accN[r], wn.x, h2[r].x); fma2(accN[r], wn.y, h2[r].y);
            }
        }
    }

    float ir = g_gi[t], iz = g_gi[D + t], in_ = g_gi[2 * D + t];
    float bhr = b_hh[t], bhz = b_hh[D + t], bhn = b_hh[2 * D + t];
#pragma unroll
    for (int r = 0; r < RT; r++) {
        float rg = sigmoidf_(ir + unpack_sum(accR[r]) + bhr);
        float zg = sigmoidf_(iz + unpack_sum(accZ[r]) + bhz);
        float ng = tanhf(in_ + rg * (unpack_sum(accN[r]) + bhn));
        s_rj[r * D + t] = (1.0f - zg) * ng + zg * s_h[r * D + t];
    }

    u64 accO[RT];
#pragma unroll
    for (int r = 0; r < RT; r++) accO[r] = 0;

    for (int tile = 0; tile < NTILE; tile++) {
        __syncthreads();
#pragma unroll
        for (int i = 0; i < (D * KT / 4) / 256; i++) {       // 8 float4 per thread
            int lin = (i * 256 + t) * 4;
            int row = lin / KT;
            int k   = lin % KT;
            float4 v = *reinterpret_cast<const float4*>(
                &obj_W[(size_t)row * D + tile * KT + k]);
            *reinterpret_cast<float4*>(&sW[row * PAD + k]) = v;
        }
        __syncthreads();
#pragma unroll
        for (int kk = 0; kk < KT; kk += 4) {
            int kg = tile * KT + kk;
            ulonglong2 wo = *reinterpret_cast<const ulonglong2*>(&sW[t * PAD + kk]);
#pragma unroll
            for (int r = 0; r < RT; r++) {
                ulonglong2 h2 = *reinterpret_cast<const ulonglong2*>(&s_rj[r * D + kg]);
                fma2(accO[r], wo.x, h2.x); fma2(accO[r], wo.y, h2.y);
            }
        }
    }

    float ob = obj_b[t];
#pragma unroll
    for (int r = 0; r < RT; r++) {
        if (rbase + r < R)
            g_obj[(size_t)(rbase + r) * D + t] = tanhf(unpack_sum(accO[r]) + ob);
    }
}

#define REL_SMEM ((3 * D * PAD + 2 * RT * D) * 4)

// ---------------------------------------------------------------------------
// Ent-scatter (side stream, no compute deps): rows with state==1.
// 18 regs / 0 smem -> co-resides with k_rel during overlap.
// ---------------------------------------------------------------------------
__global__ void k_scat_ent(const float* __restrict__ ent_table, const int* __restrict__ tail_ids,
                           const int* __restrict__ tails_state, const int* __restrict__ origin_ids,
                           float* __restrict__ out, int E) {
    int warp = threadIdx.x >> 5;
    int lane = threadIdx.x & 31;
    int base = (blockIdx.x * 8 + warp) * 4;

    float4 v[4][2];
    float4* dst[4];
    bool ok[4];
#pragma unroll
    for (int i = 0; i < 4; i++) {
        int row = base + i;
        ok[i] = (row < E) && (tails_state[row] == 1);
        if (ok[i]) {
            const float4* src = reinterpret_cast<const float4*>(ent_table)
                                + (size_t)origin_ids[row] * (D / 4);
            dst[i] = reinterpret_cast<float4*>(out) + (size_t)tail_ids[row] * (D / 4);
            v[i][0] = src[lane];
            v[i][1] = src[lane + 32];
        }
    }
#pragma unroll
    for (int i = 0; i < 4; i++) {
        if (ok[i]) {
            __stcs(&dst[i][lane], v[i][0]);
            __stcs(&dst[i][lane + 32], v[i][1]);
        }
    }
}

// ---------------------------------------------------------------------------
// Obj-scatter (after join): rows with state!=1; g_obj is L2-resident.
// Seed row folded into block 0 (seed==E never collides with tails 0..E-1).
// ---------------------------------------------------------------------------
__global__ void k_scat_obj(const int* __restrict__ rel_ids, const int* __restrict__ tail_ids,
                           const int* __restrict__ tails_state, const int* __restrict__ seed_p,
                           float* __restrict__ out, int E) {
    if (blockIdx.x == 0) {
        int seed = *seed_p;
        out[(size_t)seed * D + threadIdx.x] = g_sub[threadIdx.x];
    }

    int warp = threadIdx.x >> 5;
    int lane = threadIdx.x & 31;
    int base = (blockIdx.x * 8 + warp) * 4;

    float4 v[4][2];
    float4* dst[4];
    bool ok[4];
#pragma unroll
    for (int i = 0; i < 4; i++) {
        int row = base + i;
        ok[i] = (row < E) && (tails_state[row] != 1);
        if (ok[i]) {
            const float4* src = reinterpret_cast<const float4*>(g_obj)
                                + (size_t)rel_ids[row] * (D / 4);
            dst[i] = reinterpret_cast<float4*>(out) + (size_t)tail_ids[row] * (D / 4);
            v[i][0] = src[lane];
            v[i][1] = src[lane + 32];
        }
    }
#pragma unroll
    for (int i = 0; i < 4; i++) {
        if (ok[i]) {
            __stcs(&dst[i][lane], v[i][0]);
            __stcs(&dst[i][lane + 32], v[i][1]);
        }
    }
}

// ---------------------------------------------------------------------------
extern "C" void kernel_launch(void* const* d_in, const int* in_sizes, int n_in,
                              void* d_out, int out_size) {
    const float* enc       = (const float*)d_in[0];
    const float* mask      = (const float*)d_in[1];
    const float* ent_table = (const float*)d_in[2];
    const float* rel_table = (const float*)d_in[3];
    const float* W_ih      = (const float*)d_in[4];
    const float* W_hh      = (const float*)d_in[5];
    const float* b_ih      = (const float*)d_in[6];
    const float* b_hh      = (const float*)d_in[7];
    const float* sub_W     = (const float*)d_in[8];
    const float* sub_b     = (const float*)d_in[9];
    const float* obj_W     = (const float*)d_in[10];
    const float* obj_b     = (const float*)d_in[11];
    const int*   rel_ids   = (const int*)d_in[12];
    const int*   tail_ids  = (const int*)d_in[13];
    const int*   tails_st  = (const int*)d_in[14];
    const int*   origin    = (const int*)d_in[15];
    const int*   seed_p    = (const int*)d_in[16];
    float* out = (float*)d_out;

    int E = in_sizes[12];
    int R = in_sizes[3] / D;

    static cudaStream_t s1 = nullptr;
    static cudaEvent_t ev0 = nullptr, ev1 = nullptr;
    if (s1 == nullptr) {
        cudaStreamCreateWithFlags(&s1, cudaStreamNonBlocking);
        cudaEventCreateWithFlags(&ev0, cudaEventDisableTiming);
        cudaEventCreateWithFlags(&ev1, cudaEventDisableTiming);
        cudaFuncSetAttribute(k_rel, cudaFuncAttributeMaxDynamicSharedMemorySize, REL_SMEM);
    }

    // Fork: ent-scatter (pure HBM, no deps) on side stream s1.
    cudaEventRecord(ev0, 0);
    cudaStreamWaitEvent(s1, ev0, 0);
    k_scat_ent<<<(E + 31) / 32, 256, 0, s1>>>(ent_table, tail_ids, tails_st, origin, out, E);
    cudaEventRecord(ev1, s1);

    // Compute chain on the main (captured) stream, concurrent with ent-scatter.
    kA_sub<<<32, 256>>>(mask, sub_W, sub_b);
    kB_r0<<<32, 256>>>(enc, W_ih, W_hh, b_ih, b_hh);
    kC_gi<<<96, 256>>>(W_ih, b_ih);
    k_rel<<<(R + RT - 1) / RT, 256, REL_SMEM>>>(rel_table, W_hh, b_hh, obj_W, obj_b, R);

    // Join, then obj-scatter (+seed).
    cudaStreamWaitEvent(0, ev1, 0);
    k_scat_obj<<<(E + 31) / 32, 256>>>(rel_ids, tail_ids, tails_st, seed_p, out, E);
}

// round 9
// speedup vs baseline: 1.1150x; 1.1150x over previous
#include <cuda_runtime.h>
#include <cstdint>

#define D 256
#define RT 8        // relations per block in k_rel
#define KT2 16      // k-tile width per stage (double-buffered)
#define PADB 20     // smem row stride (floats): 5 quads/row -> exactly-4-wavefront LDS/STS
#define NT2 (D / KT2)
#define BUFF (768 * PADB)

typedef unsigned long long u64;

// Scratch (no cudaMalloc allowed).
__device__ float g_sub[D];
__device__ float g_pA[3 * D];
__device__ float g_pB[3 * D];
__device__ float g_gi[3 * D];
__device__ float g_obj[2048 * D];   // supports up to R=2048 (problem has R=1000)
__device__ int g_c1, g_c2;          // prolog spin-barrier counters (reset by k_rel)

__device__ __forceinline__ float sigmoidf_(float x) { return 1.0f / (1.0f + expf(-x)); }

__device__ __forceinline__ float wredsum(float v) {
#pragma unroll
    for (int o = 16; o; o >>= 1) v += __shfl_xor_sync(0xffffffffu, v, o);
    return v;
}

__device__ __forceinline__ void fma2(u64& acc, u64 a, u64 b) {
    asm("fma.rn.f32x2 %0, %1, %2, %3;" : "=l"(acc) : "l"(a), "l"(b), "l"(acc));
}
__device__ __forceinline__ float unpack_sum(u64 acc) {
    float lo = __uint_as_float((unsigned)(acc & 0xffffffffu));
    float hi = __uint_as_float((unsigned)(acc >> 32));
    return lo + hi;
}

__device__ __forceinline__ void cpasync16(uint32_t dst_smem, const void* src) {
    asm volatile("cp.async.cg.shared.global [%0], [%1], 16;" :: "r"(dst_smem), "l"(src));
}
__device__ __forceinline__ void cp_commit() { asm volatile("cp.async.commit_group;"); }
__device__ __forceinline__ void cp_wait1() { asm volatile("cp.async.wait_group 1;" ::: "memory"); }
__device__ __forceinline__ void cp_wait0() { asm volatile("cp.async.wait_group 0;" ::: "memory"); }

// Grid-wide spin barrier for the fused prolog. All 96 blocks are co-resident
// (96 < 148 SMs, tiny smem/regs), so spinning is deadlock-free. Counters are
// monotonic within a launch; k_rel (stream-ordered after) resets them to 0.
__device__ __forceinline__ void gbar(int* c, int n) {
    __threadfence();
    __syncthreads();
    if (threadIdx.x == 0) {
        atomicAdd(c, 1);
        while (atomicAdd(c, 0) < n) { }
    }
    __syncthreads();
}

// Coalesced warp dot: W row (256 floats) with vector x (global or shared).
__device__ __forceinline__ float warp_dot256(const float* __restrict__ Wrow,
                                             const float* x, int lane) {
    const float4* w4 = reinterpret_cast<const float4*>(Wrow);
    const float4* x4 = reinterpret_cast<const float4*>(x);
    float4 a0 = w4[lane],      b0 = x4[lane];
    float4 a1 = w4[lane + 32], b1 = x4[lane + 32];
    float s = a0.x * b0.x + a0.y * b0.y + a0.z * b0.z + a0.w * b0.w
            + a1.x * b1.x + a1.y * b1.y + a1.z * b1.z + a1.w * b1.w;
    return wredsum(s);
}

// Same, but x read via __ldcg (L2) — for cross-phase data inside the fused prolog.
__device__ __forceinline__ float warp_dot256_cg(const float* __restrict__ Wrow,
                                                const float* x, int lane) {
    const float4* w4 = reinterpret_cast<const float4*>(Wrow);
    const float4* x4 = reinterpret_cast<const float4*>(x);
    float4 a0 = w4[lane],      b0 = __ldcg(&x4[lane]);
    float4 a1 = w4[lane + 32], b1 = __ldcg(&x4[lane + 32]);
    float s = a0.x * b0.x + a0.y * b0.y + a0.z * b0.z + a0.w * b0.w
            + a1.x * b1.x + a1.y * b1.y + a1.z * b1.z + a1.w * b1.w;
    return wredsum(s);
}

// ---------------------------------------------------------------------------
// Fused prolog: one kernel, 96 blocks x 256 threads, 768 warps.
//  A: warps of blocks 0..31 -> sub = tanh(sub_W@mask+sub_b)         [barrier]
//  B: warp (g,j) -> partial gi/gh dots for GRU(enc, sub)            [barrier]
//  r0: every block redundantly combines partials -> s_r0 (smem, no barrier)
//  C: warp row -> g_gi[row] = W_ih[row]·r0 + b_ih[row]
// ---------------------------------------------------------------------------
__global__ void k_prolog(const float* __restrict__ enc, const float* __restrict__ mask,
                         const float* __restrict__ W_ih, const float* __restrict__ W_hh,
                         const float* __restrict__ b_ih, const float* __restrict__ b_hh,
                         const float* __restrict__ sub_W, const float* __restrict__ sub_b) {
    __shared__ float s_r0[D];
    int t = threadIdx.x;
    int lane = t & 31;
    int wglob = blockIdx.x * 8 + (t >> 5);   // 0..767

    // Phase A (blocks 0..31: wglob == output dim j, 0..255)
    if (blockIdx.x < 32) {
        int j = wglob;
        float s = warp_dot256(sub_W + (size_t)j * D, mask, lane);
        if (lane == 0) g_sub[j] = tanhf(s + sub_b[j]);
    }
    gbar(&g_c1, 96);

    // Phase B: row = wglob over all 3*256 gate rows
    {
        int row = wglob;
        float gi = warp_dot256(W_ih + (size_t)row * D, enc, lane);
        float gh = warp_dot256_cg(W_hh + (size_t)row * D, g_sub, lane);
        if (lane == 0) {
            g_pA[row] = gi + b_ih[row];
            g_pB[row] = gh + b_hh[row];
        }
    }
    gbar(&g_c2, 96);

    // r0 combine (redundant per block, into smem)
    {
        float ar = __ldcg(&g_pA[t])         , hr = __ldcg(&g_pB[t]);
        float az = __ldcg(&g_pA[D + t])     , hz = __ldcg(&g_pB[D + t]);
        float an = __ldcg(&g_pA[2 * D + t]) , hn = __ldcg(&g_pB[2 * D + t]);
        float sub = __ldcg(&g_sub[t]);
        float rg = sigmoidf_(ar + hr);
        float zg = sigmoidf_(az + hz);
        float ng = tanhf(an + rg * hn);
        s_r0[t] = (1.0f - zg) * ng + zg * sub;
    }
    __syncthreads();

    // Phase C
    {
        int row = wglob;
        float s = warp_dot256(W_ih + (size_t)row * D, s_r0, lane);
        if (lane == 0) g_gi[row] = s + b_ih[row];
    }
}

// ---------------------------------------------------------------------------
// k_rel v8: R3's proven register tile (3 gates x 8 rel, packed f32x2) with
// DOUBLE-BUFFERED cp.async W staging (KT=16) to overlap L2 fetch with compute.
// h-loads are warp-broadcast LDS (free); w-loads conflict-free (PADB=20).
// smem = 2 x 60KB buffers + s_h + s_rj = 136KB -> 1 CTA/SM, grid 125.
// ---------------------------------------------------------------------------
__global__ void __launch_bounds__(256, 1)
k_rel(const float* __restrict__ rel_table, const float* __restrict__ W_hh,
      const float* __restrict__ b_hh, const float* __restrict__ obj_W,
      const float* __restrict__ obj_b, int R) {
    extern __shared__ float sm[];
    float* bufp[2] = { sm, sm + BUFF };
    float* s_h  = sm + 2 * BUFF;          // RT * D
    float* s_rj = s_h + RT * D;           // RT * D
    uint32_t sbase = (uint32_t)__cvta_generic_to_shared(sm);
    uint32_t bufs[2] = { sbase, sbase + BUFF * 4 };

    // Reset prolog barrier counters for the NEXT launch sequence (stream-ordered).
    if (blockIdx.x == 0 && threadIdx.x == 0) { g_c1 = 0; g_c2 = 0; }

    int t = threadIdx.x;
    int rbase = blockIdx.x * RT;

    // --- prefetch gate tile 0 (12 x 16B per thread, coalesced row-major) ---
#pragma unroll
    for (int i = 0; i < 12; i++) {
        int f4 = i * 256 + t;            // 0..3071
        int row = f4 >> 2;               // 0..767
        int kq  = f4 & 3;
        cpasync16(bufs[0] + (row * PADB + kq * 4) * 4,
                  W_hh + (size_t)row * D + 0 * KT2 + kq * 4);
    }
    cp_commit();

    // stage h vectors (coalesced)
#pragma unroll
    for (int r = 0; r < RT; r++)
        s_h[r * D + t] = (rbase + r < R) ? rel_table[(size_t)(rbase + r) * D + t] : 0.0f;

    u64 aR[RT], aZ[RT], aN[RT];
#pragma unroll
    for (int r = 0; r < RT; r++) { aR[r] = 0; aZ[r] = 0; aN[r] = 0; }

    // ---- gate phase: 16 tiles, double-buffered ----
    for (int tile = 0; tile < NT2; tile++) {
        if (tile + 1 < NT2) {
#pragma unroll
            for (int i = 0; i < 12; i++) {
                int f4 = i * 256 + t;
                int row = f4 >> 2;
                int kq  = f4 & 3;
                cpasync16(bufs[(tile + 1) & 1] + (row * PADB + kq * 4) * 4,
                          W_hh + (size_t)row * D + (tile + 1) * KT2 + kq * 4);
            }
            cp_commit();
            cp_wait1();
        } else {
            cp_wait0();
        }
        __syncthreads();
        const float* b = bufp[tile & 1];
#pragma unroll
        for (int kk = 0; kk < KT2; kk += 4) {
            int kg = tile * KT2 + kk;
            ulonglong2 wr = *reinterpret_cast<const ulonglong2*>(&b[(0 * D + t) * PADB + kk]);
            ulonglong2 wz = *reinterpret_cast<const ulonglong2*>(&b[(1 * D + t) * PADB + kk]);
            ulonglong2 wn = *reinterpret_cast<const ulonglong2*>(&b[(2 * D + t) * PADB + kk]);
#pragma unroll
            for (int r = 0; r < RT; r++) {
                ulonglong2 h2 = *reinterpret_cast<const ulonglong2*>(&s_h[r * D + kg]);
                fma2(aR[r], wr.x, h2.x); fma2(aR[r], wr.y, h2.y);
                fma2(aZ[r], wz.x, h2.x); fma2(aZ[r], wz.y, h2.y);
                fma2(aN[r], wn.x, h2.x); fma2(aN[r], wn.y, h2.y);
            }
        }
        __syncthreads();
    }

    // ---- GRU combine -> s_rj ----
    {
        float ir = g_gi[t], iz = g_gi[D + t], in_ = g_gi[2 * D + t];
        float bhr = b_hh[t], bhz = b_hh[D + t], bhn = b_hh[2 * D + t];
#pragma unroll
        for (int r = 0; r < RT; r++) {
            float rg = sigmoidf_(ir + unpack_sum(aR[r]) + bhr);
            float zg = sigmoidf_(iz + unpack_sum(aZ[r]) + bhz);
            float ng = tanhf(in_ + rg * (unpack_sum(aN[r]) + bhn));
            s_rj[r * D + t] = (1.0f - zg) * ng + zg * s_h[r * D + t];
        }
    }

    // prefetch obj tile 0
#pragma unroll
    for (int i = 0; i < 4; i++) {
        int f4 = i * 256 + t;            // 0..1023
        int row = f4 >> 2;               // 0..255
        int kq  = f4 & 3;
        cpasync16(bufs[0] + (row * PADB + kq * 4) * 4,
                  obj_W + (size_t)row * D + 0 * KT2 + kq * 4);
    }
    cp_commit();

    u64 aO[RT];
#pragma unroll
    for (int r = 0; r < RT; r++) aO[r] = 0;

    // ---- obj phase: 16 tiles, double-buffered ----
    for (int tile = 0; tile < NT2; tile++) {
        if (tile + 1 < NT2) {
#pragma unroll
            for (int i = 0; i < 4; i++) {
                int f4 = i * 256 + t;
                int row = f4 >> 2;
                int kq  = f4 & 3;
                cpasync16(bufs[(tile + 1) & 1] + (row * PADB + kq * 4) * 4,
                          obj_W + (size_t)row * D + (tile + 1) * KT2 + kq * 4);
            }
            cp_commit();
            cp_wait1();
        } else {
            cp_wait0();
        }
        __syncthreads();   // also orders s_rj writes before reads (tile 0)
        const float* b = bufp[tile & 1];
#pragma unroll
        for (int kk = 0; kk < KT2; kk += 4) {
            int kg = tile * KT2 + kk;
            ulonglong2 wo = *reinterpret_cast<const ulonglong2*>(&b[t * PADB + kk]);
#pragma unroll
            for (int r = 0; r < RT; r++) {
                ulonglong2 h2 = *reinterpret_cast<const ulonglong2*>(&s_rj[r * D + kg]);
                fma2(aO[r], wo.x, h2.x); fma2(aO[r], wo.y, h2.y);
            }
        }
        __syncthreads();
    }

    float ob = obj_b[t];
#pragma unroll
    for (int r = 0; r < RT; r++) {
        if (rbase + r < R)
            g_obj[(size_t)(rbase + r) * D + t] = tanhf(unpack_sum(aO[r]) + ob);
    }
}

#define REL_SMEM ((2 * BUFF + 2 * RT * D) * 4)

// ---------------------------------------------------------------------------
// Single-pass scatter (+ seed row in block 0; seed==E never collides with
// tail_ids==0..E-1). Warp: 4 rows x 2 float4/lane, loads batched; __stcs.
// ---------------------------------------------------------------------------
__global__ void k_scatter(const float* __restrict__ ent_table, const int* __restrict__ rel_ids,
                          const int* __restrict__ tail_ids, const int* __restrict__ tails_state,
                          const int* __restrict__ origin_ids, const int* __restrict__ seed_p,
                          float* __restrict__ out, int E) {
    if (blockIdx.x == 0) {
        int seed = *seed_p;
        out[(size_t)seed * D + threadIdx.x] = g_sub[threadIdx.x];
    }

    int warp = threadIdx.x >> 5;
    int lane = threadIdx.x & 31;
    int base = (blockIdx.x * 8 + warp) * 4;

    float4 v[4][2];
    float4* dst[4];
    bool ok[4];
#pragma unroll
    for (int i = 0; i < 4; i++) {
        int row = base + i;
        ok[i] = row < E;
        if (ok[i]) {
            int st = tails_state[row];
            const float4* src = (st == 1)
                ? reinterpret_cast<const float4*>(ent_table) + (size_t)origin_ids[row] * (D / 4)
                : reinterpret_cast<const float4*>(g_obj) + (size_t)rel_ids[row] * (D / 4);
            dst[i] = reinterpret_cast<float4*>(out) + (size_t)tail_ids[row] * (D / 4);
            v[i][0] = src[lane];
            v[i][1] = src[lane + 32];
        }
    }
#pragma unroll
    for (int i = 0; i < 4; i++) {
        if (ok[i]) {
            __stcs(&dst[i][lane], v[i][0]);
            __stcs(&dst[i][lane + 32], v[i][1]);
        }
    }
}

// ---------------------------------------------------------------------------
extern "C" void kernel_launch(void* const* d_in, const int* in_sizes, int n_in,
                              void* d_out, int out_size) {
    const float* enc       = (const float*)d_in[0];
    const float* mask      = (const float*)d_in[1];
    const float* ent_table = (const float*)d_in[2];
    const float* rel_table = (const float*)d_in[3];
    const float* W_ih      = (const float*)d_in[4];
    const float* W_hh      = (const float*)d_in[5];
    const float* b_ih      = (const float*)d_in[6];
    const float* b_hh      = (const float*)d_in[7];
    const float* sub_W     = (const float*)d_in[8];
    const float* sub_b     = (const float*)d_in[9];
    const float* obj_W     = (const float*)d_in[10];
    const float* obj_b     = (const float*)d_in[11];
    const int*   rel_ids   = (const int*)d_in[12];
    const int*   tail_ids  = (const int*)d_in[13];
    const int*   tails_st  = (const int*)d_in[14];
    const int*   origin    = (const int*)d_in[15];
    const int*   seed_p    = (const int*)d_in[16];
    float* out = (float*)d_out;

    int E = in_sizes[12];
    int R = in_sizes[3] / D;

    static bool init = false;
    if (!init) {
        cudaFuncSetAttribute(k_rel, cudaFuncAttributeMaxDynamicSharedMemorySize, REL_SMEM);
        init = true;
    }

    k_prolog<<<96, 256>>>(enc, mask, W_ih, W_hh, b_ih, b_hh, sub_W, sub_b);
    k_rel<<<(R + RT - 1) / RT, 256, REL_SMEM>>>(rel_table, W_hh, b_hh, obj_W, obj_b, R);
    k_scatter<<<(E + 31) / 32, 256>>>(ent_table, rel_ids, tail_ids, tails_st, origin,
                                      seed_p, out, E);
}